// round 1
// baseline (speedup 1.0000x reference)
#include <cuda_runtime.h>
#include <math.h>

// ---------------------------------------------------------------------------
// CompressedSensingInception on GB300.
// Structure:
//   k_g     : factor mat = kron(ghat, ghat)  -> ghat (72x9) from diagonal sqrt
//   k_pre   : per-batch small stuff: w channel, y branch, lambda (z branch), im
//   k_fista : 96 CTAs (one per (b,c)), 100 FISTA iterations fully in SMEM
//   k_c51/k_c15/k_c55/k_x2 : post-FISTA conv chain
// Output layout: out (32,9,9,41) at d_out[0..106271], cs_out (32,72,72,3) after.
// ---------------------------------------------------------------------------

#define BNS 0.9995003746877732f   // 1/sqrt(1+1e-3)

static __device__ __forceinline__ float leakyf(float v) { return v >= 0.f ? v : 0.3f * v; }

__device__ float g_ghat[648];          // [i*9+a]
__device__ float g_lam[32];
__device__ float g_im[96 * 81];        // [(b*3+c)*81 + p]
__device__ float g_cs[32 * 5184 * 3];  // (B,72,72,3)
__device__ float g_t1[32 * 36 * 36 * 16];
__device__ float g_t2[32 * 18 * 18 * 32];
__device__ float g_t3[32 * 9 * 9 * 64];

// --------------------------- ghat extraction --------------------------------
__global__ void k_g(const float* __restrict__ mat) {
    int t = threadIdx.x;               // 648 threads
    int i = t / 9, a = t % 9;
    float v = mat[(i * 72 + i) * 81 + (a * 9 + a)];
    g_ghat[t] = sqrtf(fmaxf(v, 0.f));
}

// --------------------------- per-batch preamble -----------------------------
__global__ void k_pre(const float* __restrict__ inp,
                      const float* __restrict__ w1_k, const float* __restrict__ w1_b,
                      const float* __restrict__ x1_k, const float* __restrict__ x1_b,
                      const float* __restrict__ y17_k, const float* __restrict__ y17_b,
                      const float* __restrict__ y71_k, const float* __restrict__ y71_b,
                      const float* __restrict__ yc_k, const float* __restrict__ yc_b,
                      const float* __restrict__ d1_k, const float* __restrict__ d2_k,
                      const float* __restrict__ h1_w, const float* __restrict__ h1_b,
                      const float* __restrict__ h2_w, const float* __restrict__ h2_b,
                      const float* __restrict__ h3_w, const float* __restrict__ h3_b,
                      float* __restrict__ out) {
    __shared__ float s_in[243], s_den[27];
    __shared__ float s_y1[2592], s_y2[2592];
    __shared__ float s_z1[108], s_z2[24], s_z3[24], s_z4[12];
    const int b = blockIdx.x, tid = threadIdx.x;
    const float* ib = inp + b * 243;

    for (int k = tid; k < 243; k += blockDim.x) s_in[k] = ib[k];
    __syncthreads();

    // w channel (ch 0) and per-(w,c) max over h
    if (tid < 81) {
        float v = w1_b[0];
        #pragma unroll
        for (int c = 0; c < 3; c++) v += s_in[tid * 3 + c] * w1_k[c];
        out[(b * 81 + tid) * 41] = leakyf(v);
    } else if (tid >= 96 && tid < 123) {
        int wc = tid - 96;
        float m = 0.f;
        #pragma unroll
        for (int h = 0; h < 9; h++) m = fmaxf(m, fabsf(s_in[h * 27 + wc]));
        s_den[wc] = 0.001f + m;
    }
    __syncthreads();

    // im[b,c,p]: normalized input -> 1x1 conv (3->3) + leaky
    for (int k = tid; k < 243; k += blockDim.x) {
        int p = k / 3, o = k % 3;
        int w = p % 9;
        float v = x1_b[o];
        #pragma unroll
        for (int c = 0; c < 3; c++)
            v += (s_in[p * 3 + c] / s_den[w * 3 + c]) * x1_k[c * 3 + o];
        g_im[(b * 3 + o) * 81 + p] = leakyf(v);
    }

    // y1 (1x7), y2 (7x1), SAME pad lo=3
    for (int k = tid; k < 2592; k += blockDim.x) {
        int p = k >> 5, o = k & 31;
        int h = p / 9, w = p % 9;
        float v1 = y17_b[o], v2 = y71_b[o];
        #pragma unroll
        for (int kk = 0; kk < 7; kk++) {
            int ww = w + kk - 3;
            if (ww >= 0 && ww < 9) {
                #pragma unroll
                for (int c = 0; c < 3; c++)
                    v1 += s_in[(h * 9 + ww) * 3 + c] * y17_k[(kk * 3 + c) * 32 + o];
            }
            int hh = h + kk - 3;
            if (hh >= 0 && hh < 9) {
                #pragma unroll
                for (int c = 0; c < 3; c++)
                    v2 += s_in[(hh * 9 + w) * 3 + c] * y71_k[(kk * 3 + c) * 32 + o];
            }
        }
        s_y1[k] = v1;
        s_y2[k] = v2;
    }

    // z branch: d1 (5x5 s3 SAME, pad lo=1), BN scale + leaky, no bias
    if (tid < 108) {
        int f = tid % 12, q = tid / 12;
        int oh = q / 3, ow = q % 3;
        float acc = 0.f;
        for (int kh = 0; kh < 5; kh++) {
            int h = oh * 3 - 1 + kh;
            if (h < 0 || h > 8) continue;
            for (int kw = 0; kw < 5; kw++) {
                int w = ow * 3 - 1 + kw;
                if (w < 0 || w > 8) continue;
                #pragma unroll
                for (int c = 0; c < 3; c++)
                    acc += (s_in[(h * 9 + w) * 3 + c] * BNS) * d1_k[((kh * 5 + kw) * 3 + c) * 12 + f];
            }
        }
        s_z1[q * 12 + f] = leakyf(acc * BNS);
    }
    __syncthreads();

    // yc: 1x1 conv on concat[y1,y2] (64 -> 32), leaky  -> channels 9..40
    for (int k = tid; k < 2592; k += blockDim.x) {
        int p = k >> 5, o = k & 31;
        float v = yc_b[o];
        #pragma unroll 8
        for (int c = 0; c < 32; c++)
            v += s_y1[p * 32 + c] * yc_k[c * 32 + o] + s_y2[p * 32 + c] * yc_k[(32 + c) * 32 + o];
        out[(b * 81 + p) * 41 + 9 + o] = leakyf(v);
    }

    // d2 (5x5 s3 SAME on 3x3 -> 1x1, pad lo=1 => kh,kw in 1..3)
    if (tid < 24) {
        float acc = 0.f;
        for (int kh = 1; kh < 4; kh++)
            for (int kw = 1; kw < 4; kw++)
                #pragma unroll
                for (int c = 0; c < 12; c++)
                    acc += s_z1[((kh - 1) * 3 + (kw - 1)) * 12 + c] * d2_k[((kh * 5 + kw) * 12 + c) * 24 + tid];
        s_z2[tid] = leakyf(acc * BNS);
    }
    __syncthreads();
    if (tid < 24) {
        float v = h1_b[tid];
        #pragma unroll
        for (int f = 0; f < 24; f++) v += s_z2[f] * h1_w[f * 24 + tid];
        s_z3[tid] = v;
    }
    __syncthreads();
    if (tid < 12) {
        float v = h2_b[tid];
        #pragma unroll
        for (int f = 0; f < 24; f++) v += s_z3[f] * h2_w[f * 12 + tid];
        s_z4[tid] = v;
    }
    __syncthreads();
    if (tid == 0) {
        float s = h3_b[0];
        #pragma unroll
        for (int f = 0; f < 12; f++) s += s_z4[f] * h3_w[f];
        g_lam[b] = 0.01f / (1.f + expf(-s));   // lam = 0.1*sigmoid(s) * 0.1
    }
}

// --------------------------- FISTA (the hot loop) ---------------------------
// One CTA per (b,c). Y lives in SMEM for all 100 iterations.
//  A: P[a][j] = sum_i G[i][a] Y[i][j]          (9x72, K=72)
//  B: R[a][b] = im[a][b] - sum_j P[a][j] G[j][b]
//  C: Q[a][j] = sum_b R[a][b] G[j][b]
//  D: wv = Y + G Q ; soft-threshold ; momentum
__global__ void __launch_bounds__(576, 1) k_fista(float* __restrict__ cs_extra) {
    __shared__ float sY[5184], sYl[5184];
    __shared__ float sG[648], sPQ[648], sR[81], sIm[81];
    const int tid = threadIdx.x;
    const int bc = blockIdx.x;             // b*3 + c

    for (int k = tid; k < 648; k += 576) sG[k] = g_ghat[k];
    for (int k = tid; k < 5184; k += 576) { sY[k] = 0.f; sYl[k] = 0.f; }
    if (tid < 81) sIm[tid] = g_im[bc * 81 + tid];
    const float lam = g_lam[bc / 3];
    __syncthreads();

    // step-D ownership: thread owns row i_d, 9 consecutive columns j0..j0+8
    const int i_d = tid / 8;
    const int j0 = (tid % 8) * 9;
    float Gr[9];
    #pragma unroll
    for (int a = 0; a < 9; a++) Gr[a] = sG[i_d * 9 + a];

    float t = 1.f;
    for (int it = 0; it < 100; it++) {
        // A
        for (int idx = tid; idx < 648; idx += 576) {
            int a = idx / 72, j = idx % 72;
            float acc = 0.f;
            #pragma unroll 8
            for (int i2 = 0; i2 < 72; i2++)
                acc += sG[i2 * 9 + a] * sY[i2 * 72 + j];
            sPQ[idx] = acc;
        }
        __syncthreads();
        // B
        if (tid < 81) {
            int a = tid / 9, bb = tid % 9;
            float acc = sIm[tid];
            #pragma unroll 8
            for (int j = 0; j < 72; j++)
                acc -= sPQ[a * 72 + j] * sG[j * 9 + bb];
            sR[tid] = acc;
        }
        __syncthreads();
        // C (overwrites sPQ)
        for (int idx = tid; idx < 648; idx += 576) {
            int a = idx / 72, j = idx % 72;
            float acc = 0.f;
            #pragma unroll
            for (int bb = 0; bb < 9; bb++)
                acc += sR[a * 9 + bb] * sG[j * 9 + bb];
            sPQ[idx] = acc;
        }
        __syncthreads();
        // D
        float tn = 0.5f * (1.f + sqrtf(1.f + 4.f * t * t));
        float rmom = (t - 1.f) / tn;
        t = tn;
        #pragma unroll
        for (int jj = 0; jj < 9; jj++) {
            int n = i_d * 72 + j0 + jj;
            float wv = sY[n];
            #pragma unroll
            for (int a = 0; a < 9; a++)
                wv += Gr[a] * sPQ[a * 72 + j0 + jj];
            float ynew = fmaxf(wv - lam, 0.f) - fmaxf(-wv - lam, 0.f);
            float ynext = ynew + rmom * (ynew - sYl[n]);
            sYl[n] = ynew;
            sY[n] = ynext;
        }
        __syncthreads();
    }

    // cs_out[b,i,j,c] = y_new (= sYl after last iteration)
    const int b = bc / 3, c = bc % 3;
    float* dst = g_cs + (b * 5184) * 3 + c;
    for (int k = tid; k < 5184; k += 576) dst[k * 3] = sYl[k];
    if (cs_extra) {
        float* d2 = cs_extra + (b * 5184) * 3 + c;
        for (int k = tid; k < 5184; k += 576) d2[k * 3] = sYl[k];
    }
}

// --------------------------- post-FISTA conv chain --------------------------
// c51: (5,1,3,16) stride 2, 72->36; H pad lo=1, W pad 0
__global__ void k_c51(const float* __restrict__ k51, const float* __restrict__ b51) {
    int idx = blockIdx.x * blockDim.x + threadIdx.x;
    if (idx >= 32 * 36 * 36 * 16) return;
    int o = idx & 15;
    int ow = (idx >> 4) % 36;
    int oh = (idx / (16 * 36)) % 36;
    int b = idx / (16 * 36 * 36);
    int w = 2 * ow;
    float v = b51[o];
    #pragma unroll
    for (int kh = 0; kh < 5; kh++) {
        int h = 2 * oh - 1 + kh;
        if (h < 0 || h > 71) continue;
        const float* src = g_cs + ((b * 72 + h) * 72 + w) * 3;
        #pragma unroll
        for (int c = 0; c < 3; c++)
            v += src[c] * k51[(kh * 3 + c) * 16 + o];
    }
    g_t1[idx] = v;
}

// c15: (1,5,16,32) stride 2, 36->18; W pad lo=1, H pad 0
__global__ void k_c15(const float* __restrict__ k15, const float* __restrict__ b15) {
    int idx = blockIdx.x * blockDim.x + threadIdx.x;
    if (idx >= 32 * 18 * 18 * 32) return;
    int o = idx & 31;
    int ow = (idx >> 5) % 18;
    int oh = (idx / (32 * 18)) % 18;
    int b = idx / (32 * 18 * 18);
    int h = 2 * oh;
    float v = b15[o];
    #pragma unroll
    for (int kw = 0; kw < 5; kw++) {
        int w = 2 * ow - 1 + kw;
        if (w < 0 || w > 35) continue;
        const float* src = g_t1 + ((b * 36 + h) * 36 + w) * 16;
        #pragma unroll
        for (int c = 0; c < 16; c++)
            v += src[c] * k15[(kw * 16 + c) * 32 + o];
    }
    g_t2[idx] = v;
}

// c55: (5,5,32,64) stride 2, 18->9; pad lo=1 both
__global__ void k_c55(const float* __restrict__ k55, const float* __restrict__ b55) {
    int idx = blockIdx.x * blockDim.x + threadIdx.x;
    if (idx >= 32 * 9 * 9 * 64) return;
    int o = idx & 63;
    int ow = (idx >> 6) % 9;
    int oh = (idx / (64 * 9)) % 9;
    int b = idx / (64 * 81);
    float v = b55[o];
    for (int kh = 0; kh < 5; kh++) {
        int h = 2 * oh - 1 + kh;
        if (h < 0 || h > 17) continue;
        for (int kw = 0; kw < 5; kw++) {
            int w = 2 * ow - 1 + kw;
            if (w < 0 || w > 17) continue;
            const float* src = g_t2 + ((b * 18 + h) * 18 + w) * 32;
            const float* wk = k55 + ((kh * 5 + kw) * 32) * 64 + o;
            #pragma unroll 8
            for (int c = 0; c < 32; c++)
                v += src[c] * wk[c * 64];
        }
    }
    g_t3[idx] = v;
}

// x2: 1x1 conv 64->8 + leaky -> out channels 1..8
__global__ void k_x2(const float* __restrict__ kx2, const float* __restrict__ bx2,
                     float* __restrict__ out) {
    int idx = blockIdx.x * blockDim.x + threadIdx.x;
    if (idx >= 32 * 81 * 8) return;
    int o = idx & 7;
    int p = (idx >> 3) % 81;
    int b = idx / (8 * 81);
    const float* src = g_t3 + (b * 81 + p) * 64;
    float v = bx2[o];
    #pragma unroll 8
    for (int c = 0; c < 64; c++)
        v += src[c] * kx2[c * 8 + o];
    out[(b * 81 + p) * 41 + 1 + o] = leakyf(v);
}

// ---------------------------------------------------------------------------
extern "C" void kernel_launch(void* const* d_in, const int* in_sizes, int n_in,
                              void* d_out, int out_size) {
    const float* inp  = (const float*)d_in[0];
    const float* mat  = (const float*)d_in[1];
    const float* w1_k = (const float*)d_in[2];
    const float* w1_b = (const float*)d_in[3];
    const float* x1_k = (const float*)d_in[4];
    const float* x1_b = (const float*)d_in[5];
    const float* c51_k = (const float*)d_in[6];
    const float* c51_b = (const float*)d_in[7];
    const float* c15_k = (const float*)d_in[8];
    const float* c15_b = (const float*)d_in[9];
    const float* c55_k = (const float*)d_in[10];
    const float* c55_b = (const float*)d_in[11];
    const float* x2_k = (const float*)d_in[12];
    const float* x2_b = (const float*)d_in[13];
    const float* y17_k = (const float*)d_in[14];
    const float* y17_b = (const float*)d_in[15];
    const float* y71_k = (const float*)d_in[16];
    const float* y71_b = (const float*)d_in[17];
    const float* yc_k = (const float*)d_in[18];
    const float* yc_b = (const float*)d_in[19];
    const float* d1_k = (const float*)d_in[20];
    const float* d2_k = (const float*)d_in[21];
    const float* h1_w = (const float*)d_in[22];
    const float* h1_b = (const float*)d_in[23];
    const float* h2_w = (const float*)d_in[24];
    const float* h2_b = (const float*)d_in[25];
    const float* h3_w = (const float*)d_in[26];
    const float* h3_b = (const float*)d_in[27];

    float* out = (float*)d_out;
    const int OUT1 = 32 * 9 * 9 * 41;              // 106272
    const int OUT2 = 32 * 72 * 72 * 3;             // 497664
    float* cs_extra = (out_size >= OUT1 + OUT2) ? (out + OUT1) : nullptr;

    k_g<<<1, 648>>>(mat);
    k_pre<<<32, 256>>>(inp, w1_k, w1_b, x1_k, x1_b, y17_k, y17_b, y71_k, y71_b,
                       yc_k, yc_b, d1_k, d2_k, h1_w, h1_b, h2_w, h2_b, h3_w, h3_b, out);
    k_fista<<<96, 576>>>(cs_extra);
    k_c51<<<(32 * 36 * 36 * 16 + 255) / 256, 256>>>(c51_k, c51_b);
    k_c15<<<(32 * 18 * 18 * 32 + 255) / 256, 256>>>(c15_k, c15_b);
    k_c55<<<(32 * 9 * 9 * 64 + 255) / 256, 256>>>(c55_k, c55_b);
    k_x2<<<(32 * 81 * 8 + 255) / 256, 256>>>(x2_k, x2_b, out);
}

// round 2
// speedup vs baseline: 1.5555x; 1.5555x over previous
#include <cuda_runtime.h>
#include <math.h>

// ---------------------------------------------------------------------------
// CompressedSensingInception on GB300, round 2.
//   k_pre   : blocks 0..31: per-batch small branches; block 32: ghat factor
//   k_fista : 96 CTAs (one per (b,c)), 100 FISTA iterations, SMEM-traffic-
//             engineered: Y read once per iter in A (K-split partials),
//             Y/Ylast register-resident in D, vectorized padded G/Q rows.
//   k_c51/k_c15/k_c55/k_x2 : post-FISTA conv chain
// ---------------------------------------------------------------------------

#define BNS 0.9995003746877732f   // 1/sqrt(1+1e-3)

static __device__ __forceinline__ float leakyf(float v) { return v >= 0.f ? v : 0.3f * v; }

__device__ float g_ghat[648];          // [i*9+a]
__device__ float g_lam[32];
__device__ float g_im[96 * 81];        // [(b*3+c)*81 + p]
__device__ float g_cs[32 * 5184 * 3];  // (B,72,72,3)
__device__ float g_t1[32 * 36 * 36 * 16];
__device__ float g_t2[32 * 18 * 18 * 32];
__device__ float g_t3[32 * 9 * 9 * 64];

// --------------------------- per-batch preamble + ghat -----------------------
__global__ void k_pre(const float* __restrict__ inp, const float* __restrict__ mat,
                      const float* __restrict__ w1_k, const float* __restrict__ w1_b,
                      const float* __restrict__ x1_k, const float* __restrict__ x1_b,
                      const float* __restrict__ y17_k, const float* __restrict__ y17_b,
                      const float* __restrict__ y71_k, const float* __restrict__ y71_b,
                      const float* __restrict__ yc_k, const float* __restrict__ yc_b,
                      const float* __restrict__ d1_k, const float* __restrict__ d2_k,
                      const float* __restrict__ h1_w, const float* __restrict__ h1_b,
                      const float* __restrict__ h2_w, const float* __restrict__ h2_b,
                      const float* __restrict__ h3_w, const float* __restrict__ h3_b,
                      float* __restrict__ out) {
    const int tid = threadIdx.x;
    if (blockIdx.x == 32) {
        // ghat extraction: mat = kron(ghat, ghat); diagonal entries give ghat^2
        for (int t = tid; t < 648; t += blockDim.x) {
            int i = t / 9, a = t % 9;
            float v = mat[(i * 72 + i) * 81 + (a * 9 + a)];
            g_ghat[t] = sqrtf(fmaxf(v, 0.f));
        }
        return;
    }
    __shared__ float s_in[243], s_den[27];
    __shared__ float s_y1[2592], s_y2[2592];
    __shared__ float s_z1[108], s_z2[24], s_z3[24], s_z4[12];
    const int b = blockIdx.x;
    const float* ib = inp + b * 243;

    for (int k = tid; k < 243; k += blockDim.x) s_in[k] = ib[k];
    __syncthreads();

    // w channel (ch 0) and per-(w,c) max over h
    if (tid < 81) {
        float v = w1_b[0];
        #pragma unroll
        for (int c = 0; c < 3; c++) v += s_in[tid * 3 + c] * w1_k[c];
        out[(b * 81 + tid) * 41] = leakyf(v);
    } else if (tid >= 96 && tid < 123) {
        int wc = tid - 96;
        float m = 0.f;
        #pragma unroll
        for (int h = 0; h < 9; h++) m = fmaxf(m, fabsf(s_in[h * 27 + wc]));
        s_den[wc] = 0.001f + m;
    }
    __syncthreads();

    // im[b,c,p]: normalized input -> 1x1 conv (3->3) + leaky
    for (int k = tid; k < 243; k += blockDim.x) {
        int p = k / 3, o = k % 3;
        int w = p % 9;
        float v = x1_b[o];
        #pragma unroll
        for (int c = 0; c < 3; c++)
            v += (s_in[p * 3 + c] / s_den[w * 3 + c]) * x1_k[c * 3 + o];
        g_im[(b * 3 + o) * 81 + p] = leakyf(v);
    }

    // y1 (1x7), y2 (7x1), SAME pad lo=3
    for (int k = tid; k < 2592; k += blockDim.x) {
        int p = k >> 5, o = k & 31;
        int h = p / 9, w = p % 9;
        float v1 = y17_b[o], v2 = y71_b[o];
        #pragma unroll
        for (int kk = 0; kk < 7; kk++) {
            int ww = w + kk - 3;
            if (ww >= 0 && ww < 9) {
                #pragma unroll
                for (int c = 0; c < 3; c++)
                    v1 += s_in[(h * 9 + ww) * 3 + c] * y17_k[(kk * 3 + c) * 32 + o];
            }
            int hh = h + kk - 3;
            if (hh >= 0 && hh < 9) {
                #pragma unroll
                for (int c = 0; c < 3; c++)
                    v2 += s_in[(hh * 9 + w) * 3 + c] * y71_k[(kk * 3 + c) * 32 + o];
            }
        }
        s_y1[k] = v1;
        s_y2[k] = v2;
    }

    // z branch: d1 (5x5 s3 SAME, pad lo=1), BN scale + leaky, no bias
    if (tid < 108) {
        int f = tid % 12, q = tid / 12;
        int oh = q / 3, ow = q % 3;
        float acc = 0.f;
        for (int kh = 0; kh < 5; kh++) {
            int h = oh * 3 - 1 + kh;
            if (h < 0 || h > 8) continue;
            for (int kw = 0; kw < 5; kw++) {
                int w = ow * 3 - 1 + kw;
                if (w < 0 || w > 8) continue;
                #pragma unroll
                for (int c = 0; c < 3; c++)
                    acc += (s_in[(h * 9 + w) * 3 + c] * BNS) * d1_k[((kh * 5 + kw) * 3 + c) * 12 + f];
            }
        }
        s_z1[q * 12 + f] = leakyf(acc * BNS);
    }
    __syncthreads();

    // yc: 1x1 conv on concat[y1,y2] (64 -> 32), leaky  -> channels 9..40
    for (int k = tid; k < 2592; k += blockDim.x) {
        int p = k >> 5, o = k & 31;
        float v = yc_b[o];
        #pragma unroll 8
        for (int c = 0; c < 32; c++)
            v += s_y1[p * 32 + c] * yc_k[c * 32 + o] + s_y2[p * 32 + c] * yc_k[(32 + c) * 32 + o];
        out[(b * 81 + p) * 41 + 9 + o] = leakyf(v);
    }

    // d2 (5x5 s3 SAME on 3x3 -> 1x1, pad lo=1 => kh,kw in 1..3)
    if (tid < 24) {
        float acc = 0.f;
        for (int kh = 1; kh < 4; kh++)
            for (int kw = 1; kw < 4; kw++)
                #pragma unroll
                for (int c = 0; c < 12; c++)
                    acc += s_z1[((kh - 1) * 3 + (kw - 1)) * 12 + c] * d2_k[((kh * 5 + kw) * 12 + c) * 24 + tid];
        s_z2[tid] = leakyf(acc * BNS);
    }
    __syncthreads();
    if (tid < 24) {
        float v = h1_b[tid];
        #pragma unroll
        for (int f = 0; f < 24; f++) v += s_z2[f] * h1_w[f * 24 + tid];
        s_z3[tid] = v;
    }
    __syncthreads();
    if (tid < 12) {
        float v = h2_b[tid];
        #pragma unroll
        for (int f = 0; f < 24; f++) v += s_z3[f] * h2_w[f * 12 + tid];
        s_z4[tid] = v;
    }
    __syncthreads();
    if (tid == 0) {
        float s = h3_b[0];
        #pragma unroll
        for (int f = 0; f < 12; f++) s += s_z4[f] * h3_w[f];
        g_lam[b] = 0.01f / (1.f + expf(-s));   // lam = 0.1*sigmoid(s) * 0.1
    }
}

// --------------------------- FISTA (the hot loop) ---------------------------
// One CTA per (b,c), 576 threads. Per iteration:
//  A : partials of P = ghat^T Y   (Y read exactly once, 8 i-groups x 72 cols)
//  Ar: reduce 8 partials -> sP (9x72)
//  B : R = Im - P ghat            (81 threads, vectorized P rows)
//  C : Qt[j][a] = sum_b R[a][b] ghat[j][b]   (transposed, stride-12 rows)
//  D : per-thread 9 register-resident Y/Ylast elements; wv = Y + ghat_row . Qt_row
__global__ void __launch_bounds__(576, 1) k_fista(float* __restrict__ cs_extra) {
    __shared__ __align__(16) float sY[5184];      // Y, stride 72
    __shared__ __align__(16) float sWork[5184];   // A-partials; later Qt (0..863) + R (900..1007)
    __shared__ __align__(16) float sP[648];       // P = ghat^T Y, [a*72+j]
    __shared__ __align__(16) float sG12[864];     // ghat rows padded to stride 12
    __shared__ float sIm[81];

    float* const sQt = sWork;                     // [j*12 + a]
    float* const sR  = sWork + 900;               // [a*12 + b]

    const int tid = threadIdx.x;
    const int bc = blockIdx.x;                    // b*3 + c

    for (int k = tid; k < 648; k += 576) sG12[(k / 9) * 12 + (k % 9)] = g_ghat[k];
    for (int k = tid; k < 5184; k += 576) sY[k] = 0.f;
    if (tid < 81) sIm[tid] = g_im[bc * 81 + tid];
    const float lam = g_lam[bc / 3];
    __syncthreads();

    // A ownership: grp = tid/72 (8 groups of 9 i-values), jcol = tid%72
    const int grp = tid / 72;
    const int jcol = tid % 72;
    // B ownership: 81 threads, a_b = tid/9, b_b = tid%9
    // D ownership: i_d = tid/8, j0 = (tid%8)*9 (bank-conflict-free on stride-72 Y)
    const int i_d = tid >> 3;
    const int j0 = (tid & 7) * 9;

    float Gr[9];
    #pragma unroll
    for (int a = 0; a < 9; a++) Gr[a] = sG12[i_d * 12 + a];

    float yv[9], yl[9];
    #pragma unroll
    for (int jj = 0; jj < 9; jj++) { yv[jj] = 0.f; yl[jj] = 0.f; }

    float t = 1.f;
    for (int it = 0; it < 100; it++) {
        // ---- A: partials of P. Each thread: 9 Y reads (once), G rows vectorized.
        {
            float acc[9];
            #pragma unroll
            for (int a = 0; a < 9; a++) acc[a] = 0.f;
            #pragma unroll
            for (int ii = 0; ii < 9; ii++) {
                int i = grp * 9 + ii;
                float y = sY[i * 72 + jcol];
                float4 ga = *(const float4*)&sG12[i * 12];
                float4 gb = *(const float4*)&sG12[i * 12 + 4];
                float  gc = sG12[i * 12 + 8];
                acc[0] += ga.x * y; acc[1] += ga.y * y; acc[2] += ga.z * y; acc[3] += ga.w * y;
                acc[4] += gb.x * y; acc[5] += gb.y * y; acc[6] += gb.z * y; acc[7] += gb.w * y;
                acc[8] += gc * y;
            }
            #pragma unroll
            for (int a = 0; a < 9; a++) sWork[grp * 648 + a * 72 + jcol] = acc[a];
        }
        __syncthreads();
        // ---- A-reduce: sP[a*72+j] = sum over 8 groups
        for (int idx = tid; idx < 648; idx += 576) {
            float s = 0.f;
            #pragma unroll
            for (int g = 0; g < 8; g++) s += sWork[g * 648 + idx];
            sP[idx] = s;
        }
        __syncthreads();
        // ---- B: R[a][b] = Im[a][b] - sum_j P[a][j] * ghat[j][b]
        if (tid < 81) {
            int a = tid / 9, bb = tid % 9;
            float acc = 0.f;
            #pragma unroll
            for (int j4 = 0; j4 < 72; j4 += 4) {
                float4 p = *(const float4*)&sP[a * 72 + j4];
                acc += p.x * sG12[(j4 + 0) * 12 + bb];
                acc += p.y * sG12[(j4 + 1) * 12 + bb];
                acc += p.z * sG12[(j4 + 2) * 12 + bb];
                acc += p.w * sG12[(j4 + 3) * 12 + bb];
            }
            sR[a * 12 + bb] = sIm[tid] - acc;
        }
        __syncthreads();
        // ---- C: Qt[j][a] = sum_b R[a][b] * ghat[j][b]  (store transposed)
        for (int idx = tid; idx < 648; idx += 576) {
            int a = idx / 72, j = idx % 72;
            float4 ra = *(const float4*)&sR[a * 12];
            float4 rb = *(const float4*)&sR[a * 12 + 4];
            float  rc = sR[a * 12 + 8];
            float4 ga = *(const float4*)&sG12[j * 12];
            float4 gb = *(const float4*)&sG12[j * 12 + 4];
            float  gc = sG12[j * 12 + 8];
            float q = ra.x * ga.x + ra.y * ga.y + ra.z * ga.z + ra.w * ga.w
                    + rb.x * gb.x + rb.y * gb.y + rb.z * gb.z + rb.w * gb.w
                    + rc * gc;
            sQt[j * 12 + a] = q;
        }
        __syncthreads();
        // ---- D: register-resident Y/Ylast update + soft threshold + momentum
        float tn = 0.5f * (1.f + sqrtf(1.f + 4.f * t * t));
        float rmom = (t - 1.f) / tn;
        t = tn;
        #pragma unroll
        for (int jj = 0; jj < 9; jj++) {
            int j = j0 + jj;
            float4 qa = *(const float4*)&sQt[j * 12];
            float4 qb = *(const float4*)&sQt[j * 12 + 4];
            float  qc = sQt[j * 12 + 8];
            float wv = yv[jj]
                     + Gr[0] * qa.x + Gr[1] * qa.y + Gr[2] * qa.z + Gr[3] * qa.w
                     + Gr[4] * qb.x + Gr[5] * qb.y + Gr[6] * qb.z + Gr[7] * qb.w
                     + Gr[8] * qc;
            float ynew = fmaxf(wv - lam, 0.f) - fmaxf(-wv - lam, 0.f);
            float ynext = ynew + rmom * (ynew - yl[jj]);
            yl[jj] = ynew;
            yv[jj] = ynext;
            sY[i_d * 72 + j] = ynext;
        }
        __syncthreads();
    }

    // cs_out[b,i,j,c] = y_new (yl holds ynew of last iteration)
    const int b = bc / 3, c = bc % 3;
    #pragma unroll
    for (int jj = 0; jj < 9; jj++) {
        int k = i_d * 72 + j0 + jj;
        g_cs[(b * 5184 + k) * 3 + c] = yl[jj];
    }
    if (cs_extra) {
        #pragma unroll
        for (int jj = 0; jj < 9; jj++) {
            int k = i_d * 72 + j0 + jj;
            cs_extra[(b * 5184 + k) * 3 + c] = yl[jj];
        }
    }
}

// --------------------------- post-FISTA conv chain --------------------------
// c51: (5,1,3,16) stride 2, 72->36; H pad lo=1, W pad 0
__global__ void k_c51(const float* __restrict__ k51, const float* __restrict__ b51) {
    int idx = blockIdx.x * blockDim.x + threadIdx.x;
    if (idx >= 32 * 36 * 36 * 16) return;
    int o = idx & 15;
    int ow = (idx >> 4) % 36;
    int oh = (idx / (16 * 36)) % 36;
    int b = idx / (16 * 36 * 36);
    int w = 2 * ow;
    float v = b51[o];
    #pragma unroll
    for (int kh = 0; kh < 5; kh++) {
        int h = 2 * oh - 1 + kh;
        if (h < 0 || h > 71) continue;
        const float* src = g_cs + ((b * 72 + h) * 72 + w) * 3;
        #pragma unroll
        for (int c = 0; c < 3; c++)
            v += src[c] * k51[(kh * 3 + c) * 16 + o];
    }
    g_t1[idx] = v;
}

// c15: (1,5,16,32) stride 2, 36->18; W pad lo=1, H pad 0
__global__ void k_c15(const float* __restrict__ k15, const float* __restrict__ b15) {
    int idx = blockIdx.x * blockDim.x + threadIdx.x;
    if (idx >= 32 * 18 * 18 * 32) return;
    int o = idx & 31;
    int ow = (idx >> 5) % 18;
    int oh = (idx / (32 * 18)) % 18;
    int b = idx / (32 * 18 * 18);
    int h = 2 * oh;
    float v = b15[o];
    #pragma unroll
    for (int kw = 0; kw < 5; kw++) {
        int w = 2 * ow - 1 + kw;
        if (w < 0 || w > 35) continue;
        const float* src = g_t1 + ((b * 36 + h) * 36 + w) * 16;
        #pragma unroll
        for (int c = 0; c < 16; c++)
            v += src[c] * k15[(kw * 16 + c) * 32 + o];
    }
    g_t2[idx] = v;
}

// c55: (5,5,32,64) stride 2, 18->9; pad lo=1 both
__global__ void k_c55(const float* __restrict__ k55, const float* __restrict__ b55) {
    int idx = blockIdx.x * blockDim.x + threadIdx.x;
    if (idx >= 32 * 9 * 9 * 64) return;
    int o = idx & 63;
    int ow = (idx >> 6) % 9;
    int oh = (idx / (64 * 9)) % 9;
    int b = idx / (64 * 81);
    float v = b55[o];
    for (int kh = 0; kh < 5; kh++) {
        int h = 2 * oh - 1 + kh;
        if (h < 0 || h > 17) continue;
        for (int kw = 0; kw < 5; kw++) {
            int w = 2 * ow - 1 + kw;
            if (w < 0 || w > 17) continue;
            const float* src = g_t2 + ((b * 18 + h) * 18 + w) * 32;
            const float* wk = k55 + ((kh * 5 + kw) * 32) * 64 + o;
            #pragma unroll 8
            for (int c = 0; c < 32; c++)
                v += src[c] * wk[c * 64];
        }
    }
    g_t3[idx] = v;
}

// x2: 1x1 conv 64->8 + leaky -> out channels 1..8
__global__ void k_x2(const float* __restrict__ kx2, const float* __restrict__ bx2,
                     float* __restrict__ out) {
    int idx = blockIdx.x * blockDim.x + threadIdx.x;
    if (idx >= 32 * 81 * 8) return;
    int o = idx & 7;
    int p = (idx >> 3) % 81;
    int b = idx / (8 * 81);
    const float* src = g_t3 + (b * 81 + p) * 64;
    float v = bx2[o];
    #pragma unroll 8
    for (int c = 0; c < 64; c++)
        v += src[c] * kx2[c * 8 + o];
    out[(b * 81 + p) * 41 + 1 + o] = leakyf(v);
}

// ---------------------------------------------------------------------------
extern "C" void kernel_launch(void* const* d_in, const int* in_sizes, int n_in,
                              void* d_out, int out_size) {
    const float* inp  = (const float*)d_in[0];
    const float* mat  = (const float*)d_in[1];
    const float* w1_k = (const float*)d_in[2];
    const float* w1_b = (const float*)d_in[3];
    const float* x1_k = (const float*)d_in[4];
    const float* x1_b = (const float*)d_in[5];
    const float* c51_k = (const float*)d_in[6];
    const float* c51_b = (const float*)d_in[7];
    const float* c15_k = (const float*)d_in[8];
    const float* c15_b = (const float*)d_in[9];
    const float* c55_k = (const float*)d_in[10];
    const float* c55_b = (const float*)d_in[11];
    const float* x2_k = (const float*)d_in[12];
    const float* x2_b = (const float*)d_in[13];
    const float* y17_k = (const float*)d_in[14];
    const float* y17_b = (const float*)d_in[15];
    const float* y71_k = (const float*)d_in[16];
    const float* y71_b = (const float*)d_in[17];
    const float* yc_k = (const float*)d_in[18];
    const float* yc_b = (const float*)d_in[19];
    const float* d1_k = (const float*)d_in[20];
    const float* d2_k = (const float*)d_in[21];
    const float* h1_w = (const float*)d_in[22];
    const float* h1_b = (const float*)d_in[23];
    const float* h2_w = (const float*)d_in[24];
    const float* h2_b = (const float*)d_in[25];
    const float* h3_w = (const float*)d_in[26];
    const float* h3_b = (const float*)d_in[27];

    float* out = (float*)d_out;
    const int OUT1 = 32 * 9 * 9 * 41;              // 106272
    const int OUT2 = 32 * 72 * 72 * 3;             // 497664
    float* cs_extra = (out_size >= OUT1 + OUT2) ? (out + OUT1) : nullptr;

    k_pre<<<33, 256>>>(inp, mat, w1_k, w1_b, x1_k, x1_b, y17_k, y17_b, y71_k, y71_b,
                       yc_k, yc_b, d1_k, d2_k, h1_w, h1_b, h2_w, h2_b, h3_w, h3_b, out);
    k_fista<<<96, 576>>>(cs_extra);
    k_c51<<<(32 * 36 * 36 * 16 + 255) / 256, 256>>>(c51_k, c51_b);
    k_c15<<<(32 * 18 * 18 * 32 + 255) / 256, 256>>>(c15_k, c15_b);
    k_c55<<<(32 * 9 * 9 * 64 + 255) / 256, 256>>>(c55_k, c55_b);
    k_x2<<<(32 * 81 * 8 + 255) / 256, 256>>>(x2_k, x2_b, out);
}

// round 3
// speedup vs baseline: 1.9660x; 1.2639x over previous
#include <cuda_runtime.h>
#include <math.h>

// ---------------------------------------------------------------------------
// CompressedSensingInception on GB300, round 3.
//   k_main  : grid 128. Blocks 0..95: one (b,c) FISTA problem each —
//             prologue computes ghat/im/lambda locally; 100 iterations with
//             step A fused into step D (Y fully register-resident, no sY).
//             Blocks 96..127: w-channel + y branch + yc (independent work).
//   k_c51/k_c15 : conv chain stages (unchanged)
//   k_c55x2 : c55 conv with x2 1x1-conv epilogue fused in-block.
// ---------------------------------------------------------------------------

#define BNS 0.9995003746877732f   // 1/sqrt(1+1e-3)

static __device__ __forceinline__ float leakyf(float v) { return v >= 0.f ? v : 0.3f * v; }

__device__ float g_cs[32 * 5184 * 3];  // (B,72,72,3)
__device__ float g_t1[32 * 36 * 36 * 16];
__device__ float g_t2[32 * 18 * 18 * 32];

// --------------------------- main fused kernel ------------------------------
__global__ void __launch_bounds__(576, 1) k_main(
    const float* __restrict__ inp, const float* __restrict__ mat,
    const float* __restrict__ w1_k, const float* __restrict__ w1_b,
    const float* __restrict__ x1_k, const float* __restrict__ x1_b,
    const float* __restrict__ y17_k, const float* __restrict__ y17_b,
    const float* __restrict__ y71_k, const float* __restrict__ y71_b,
    const float* __restrict__ yc_k, const float* __restrict__ yc_b,
    const float* __restrict__ d1_k, const float* __restrict__ d2_k,
    const float* __restrict__ h1_w, const float* __restrict__ h1_b,
    const float* __restrict__ h2_w, const float* __restrict__ h2_b,
    const float* __restrict__ h3_w, const float* __restrict__ h3_b,
    float* __restrict__ out, float* __restrict__ cs_extra) {

    __shared__ __align__(16) float sPart[5832];   // A-partials; prologue scratch
    __shared__ __align__(16) float sP[648];       // P = ghat^T Y, [a*72+j]
    __shared__ __align__(16) float sG12[864];     // ghat rows padded to stride 12
    __shared__ __align__(16) float sQt[720];      // Q rows padded to stride 80: [a*80+j]
    __shared__ __align__(16) float sR[108];       // [a*12+b]
    __shared__ float sIm[81];
    __shared__ float sLam[1];

    const int tid = threadIdx.x;

    // ======================= w / y / yc branch blocks =======================
    if (blockIdx.x >= 96) {
        float* s_in = sPart;           // 243
        float* s_y1 = sPart + 256;     // 2592
        float* s_y2 = sPart + 2880;    // 2592
        const int b = blockIdx.x - 96;
        for (int k = tid; k < 243; k += 576) s_in[k] = inp[b * 243 + k];
        __syncthreads();

        if (tid < 81) {  // w channel -> out ch 0
            float v = w1_b[0];
            #pragma unroll
            for (int c = 0; c < 3; c++) v += s_in[tid * 3 + c] * w1_k[c];
            out[(b * 81 + tid) * 41] = leakyf(v);
        }
        // y1 (1x7), y2 (7x1), SAME pad lo=3
        for (int k = tid; k < 2592; k += 576) {
            int p = k >> 5, o = k & 31;
            int h = p / 9, w = p % 9;
            float v1 = y17_b[o], v2 = y71_b[o];
            #pragma unroll
            for (int kk = 0; kk < 7; kk++) {
                int ww = w + kk - 3;
                if (ww >= 0 && ww < 9) {
                    #pragma unroll
                    for (int c = 0; c < 3; c++)
                        v1 += s_in[(h * 9 + ww) * 3 + c] * y17_k[(kk * 3 + c) * 32 + o];
                }
                int hh = h + kk - 3;
                if (hh >= 0 && hh < 9) {
                    #pragma unroll
                    for (int c = 0; c < 3; c++)
                        v2 += s_in[(hh * 9 + w) * 3 + c] * y71_k[(kk * 3 + c) * 32 + o];
                }
            }
            s_y1[k] = v1;
            s_y2[k] = v2;
        }
        __syncthreads();
        // yc: 1x1 conv on concat[y1,y2] (64 -> 32) -> out ch 9..40
        for (int k = tid; k < 2592; k += 576) {
            int p = k >> 5, o = k & 31;
            float v = yc_b[o];
            #pragma unroll 8
            for (int c = 0; c < 32; c++)
                v += s_y1[p * 32 + c] * yc_k[c * 32 + o] + s_y2[p * 32 + c] * yc_k[(32 + c) * 32 + o];
            out[(b * 81 + p) * 41 + 9 + o] = leakyf(v);
        }
        return;
    }

    // ============================ FISTA blocks ==============================
    const int bc = blockIdx.x;
    const int b = bc / 3, c = bc % 3;

    // prologue scratch aliased into sPart
    float* s_in  = sPart;          // 243
    float* s_den = sPart + 256;    // 27
    float* sZ1   = sPart + 288;    // 108
    float* sZ2   = sPart + 400;    // 24
    float* sZ3   = sPart + 432;    // 24
    float* sZ4   = sPart + 464;    // 12

    // ghat = sqrt of diagonal entries of mat (mat = kron(ghat, ghat), ghat>=0)
    for (int k = tid; k < 648; k += 576) {
        int i = k / 9, a = k % 9;
        float v = mat[(i * 72 + i) * 81 + (a * 9 + a)];
        sG12[i * 12 + a] = sqrtf(fmaxf(v, 0.f));
    }
    for (int k = tid; k < 243; k += 576) s_in[k] = inp[b * 243 + k];
    for (int k = tid; k < 648; k += 576) sP[k] = 0.f;   // Y=0 -> P=0
    __syncthreads();

    // stage: den (27 thr) + d1 (108 thr)
    if (tid < 27) {
        float m = 0.f;
        #pragma unroll
        for (int h = 0; h < 9; h++) m = fmaxf(m, fabsf(s_in[h * 27 + tid]));
        s_den[tid] = 0.001f + m;
    }
    if (tid >= 64 && tid < 172) {
        int tt = tid - 64;
        int f = tt % 12, q = tt / 12;
        int oh = q / 3, ow = q % 3;
        float acc = 0.f;
        for (int kh = 0; kh < 5; kh++) {
            int h = oh * 3 - 1 + kh;
            if (h < 0 || h > 8) continue;
            for (int kw = 0; kw < 5; kw++) {
                int w = ow * 3 - 1 + kw;
                if (w < 0 || w > 8) continue;
                #pragma unroll
                for (int cc = 0; cc < 3; cc++)
                    acc += (s_in[(h * 9 + w) * 3 + cc] * BNS) * d1_k[((kh * 5 + kw) * 3 + cc) * 12 + f];
            }
        }
        sZ1[q * 12 + f] = leakyf(acc * BNS);
    }
    __syncthreads();

    // stage: im (81 thr, only channel c) + d2 (24 thr)
    if (tid < 81) {
        int w = tid % 9;
        float v = x1_b[c];
        #pragma unroll
        for (int c2 = 0; c2 < 3; c2++)
            v += (s_in[tid * 3 + c2] / s_den[w * 3 + c2]) * x1_k[c2 * 3 + c];
        sIm[tid] = leakyf(v);
    }
    if (tid >= 96 && tid < 120) {
        int f = tid - 96;
        float acc = 0.f;
        for (int kh = 1; kh < 4; kh++)
            for (int kw = 1; kw < 4; kw++)
                #pragma unroll
                for (int cc = 0; cc < 12; cc++)
                    acc += sZ1[((kh - 1) * 3 + (kw - 1)) * 12 + cc] * d2_k[((kh * 5 + kw) * 12 + cc) * 24 + f];
        sZ2[f] = leakyf(acc * BNS);
    }
    __syncthreads();
    if (tid < 24) {
        float v = h1_b[tid];
        #pragma unroll
        for (int f = 0; f < 24; f++) v += sZ2[f] * h1_w[f * 24 + tid];
        sZ3[tid] = v;
    }
    __syncthreads();
    if (tid < 12) {
        float v = h2_b[tid];
        #pragma unroll
        for (int f = 0; f < 24; f++) v += sZ3[f] * h2_w[f * 12 + tid];
        sZ4[tid] = v;
    }
    __syncthreads();
    if (tid == 0) {
        float s = h3_b[0];
        #pragma unroll
        for (int f = 0; f < 12; f++) s += sZ4[f] * h3_w[f];
        sLam[0] = 0.01f / (1.f + expf(-s));   // 0.1*sigmoid * 0.1
    }
    __syncthreads();
    const float lam = sLam[0];

    // ownership: thread owns Y[grp*9+ii][j] for ii=0..8, register resident
    const int grp = tid / 72;
    const int j   = tid % 72;

    float yv[9], yl[9];
    #pragma unroll
    for (int ii = 0; ii < 9; ii++) { yv[ii] = 0.f; yl[ii] = 0.f; }

    float t = 1.f;
    for (int it = 0; it < 100; it++) {
        // ---- B: R[a][b] = Im[a][b] - sum_j P[a][j] * ghat[j][b]
        if (tid < 81) {
            int a = tid / 9, bb = tid % 9;
            float acc = 0.f;
            #pragma unroll
            for (int j4 = 0; j4 < 72; j4 += 4) {
                float4 p = *(const float4*)&sP[a * 72 + j4];
                acc += p.x * sG12[(j4 + 0) * 12 + bb];
                acc += p.y * sG12[(j4 + 1) * 12 + bb];
                acc += p.z * sG12[(j4 + 2) * 12 + bb];
                acc += p.w * sG12[(j4 + 3) * 12 + bb];
            }
            sR[a * 12 + bb] = sIm[tid] - acc;
        }
        __syncthreads();
        // ---- C: Qt[a][j2] = sum_b R[a][b] * ghat[j2][b]  (stride-80 rows)
        for (int idx = tid; idx < 648; idx += 576) {
            int a = idx / 72, j2 = idx % 72;
            float4 ra = *(const float4*)&sR[a * 12];
            float4 rb = *(const float4*)&sR[a * 12 + 4];
            float  rc = sR[a * 12 + 8];
            float4 ga = *(const float4*)&sG12[j2 * 12];
            float4 gb = *(const float4*)&sG12[j2 * 12 + 4];
            float  gc = sG12[j2 * 12 + 8];
            sQt[a * 80 + j2] = ra.x * ga.x + ra.y * ga.y + ra.z * ga.z + ra.w * ga.w
                             + rb.x * gb.x + rb.y * gb.y + rb.z * gb.z + rb.w * gb.w
                             + rc * gc;
        }
        __syncthreads();
        // ---- D + A fused: update Y in registers, emit A-partials directly
        float tn = 0.5f * (1.f + sqrtf(1.f + 4.f * t * t));
        float rmom = (t - 1.f) / tn;
        t = tn;
        float q[9];
        #pragma unroll
        for (int a = 0; a < 9; a++) q[a] = sQt[a * 80 + j];
        float acc[9];
        #pragma unroll
        for (int a = 0; a < 9; a++) acc[a] = 0.f;
        #pragma unroll
        for (int ii = 0; ii < 9; ii++) {
            int i = grp * 9 + ii;
            float4 ga = *(const float4*)&sG12[i * 12];
            float4 gb = *(const float4*)&sG12[i * 12 + 4];
            float  gc = sG12[i * 12 + 8];
            float wv = yv[ii]
                     + ga.x * q[0] + ga.y * q[1] + ga.z * q[2] + ga.w * q[3]
                     + gb.x * q[4] + gb.y * q[5] + gb.z * q[6] + gb.w * q[7]
                     + gc * q[8];
            float ynew = fmaxf(wv - lam, 0.f) - fmaxf(-wv - lam, 0.f);
            float ynext = ynew + rmom * (ynew - yl[ii]);
            yl[ii] = ynew;
            yv[ii] = ynext;
            acc[0] += ga.x * ynext; acc[1] += ga.y * ynext; acc[2] += ga.z * ynext;
            acc[3] += ga.w * ynext; acc[4] += gb.x * ynext; acc[5] += gb.y * ynext;
            acc[6] += gb.z * ynext; acc[7] += gb.w * ynext; acc[8] += gc * ynext;
        }
        #pragma unroll
        for (int a = 0; a < 9; a++) sPart[(a * 72 + j) * 9 + grp] = acc[a];
        __syncthreads();
        // ---- reduce partials -> sP
        for (int idx = tid; idx < 648; idx += 576) {
            const float* pp = &sPart[idx * 9];
            sP[idx] = ((pp[0] + pp[1]) + (pp[2] + pp[3]))
                    + ((pp[4] + pp[5]) + (pp[6] + pp[7]));
        }
        __syncthreads();
    }

    // cs_out[b,i,j,c] = y_new (yl holds ynew of last iteration)
    #pragma unroll
    for (int ii = 0; ii < 9; ii++) {
        int k = (grp * 9 + ii) * 72 + j;
        g_cs[(b * 5184 + k) * 3 + c] = yl[ii];
    }
    if (cs_extra) {
        #pragma unroll
        for (int ii = 0; ii < 9; ii++) {
            int k = (grp * 9 + ii) * 72 + j;
            cs_extra[(b * 5184 + k) * 3 + c] = yl[ii];
        }
    }
}

// --------------------------- post-FISTA conv chain --------------------------
// c51: (5,1,3,16) stride 2, 72->36; H pad lo=1, W pad 0
__global__ void k_c51(const float* __restrict__ k51, const float* __restrict__ b51) {
    int idx = blockIdx.x * blockDim.x + threadIdx.x;
    if (idx >= 32 * 36 * 36 * 16) return;
    int o = idx & 15;
    int ow = (idx >> 4) % 36;
    int oh = (idx / (16 * 36)) % 36;
    int b = idx / (16 * 36 * 36);
    int w = 2 * ow;
    float v = b51[o];
    #pragma unroll
    for (int kh = 0; kh < 5; kh++) {
        int h = 2 * oh - 1 + kh;
        if (h < 0 || h > 71) continue;
        const float* src = g_cs + ((b * 72 + h) * 72 + w) * 3;
        #pragma unroll
        for (int c = 0; c < 3; c++)
            v += src[c] * k51[(kh * 3 + c) * 16 + o];
    }
    g_t1[idx] = v;
}

// c15: (1,5,16,32) stride 2, 36->18; W pad lo=1, H pad 0
__global__ void k_c15(const float* __restrict__ k15, const float* __restrict__ b15) {
    int idx = blockIdx.x * blockDim.x + threadIdx.x;
    if (idx >= 32 * 18 * 18 * 32) return;
    int o = idx & 31;
    int ow = (idx >> 5) % 18;
    int oh = (idx / (32 * 18)) % 18;
    int b = idx / (32 * 18 * 18);
    int h = 2 * oh;
    float v = b15[o];
    #pragma unroll
    for (int kw = 0; kw < 5; kw++) {
        int w = 2 * ow - 1 + kw;
        if (w < 0 || w > 35) continue;
        const float* src = g_t1 + ((b * 36 + h) * 36 + w) * 16;
        #pragma unroll
        for (int c = 0; c < 16; c++)
            v += src[c] * k15[(kw * 16 + c) * 32 + o];
    }
    g_t2[idx] = v;
}

// c55 (5,5,32,64) stride 2, 18->9, pad lo=1, fused with x2 (1x1, 64->8, leaky)
__global__ void k_c55x2(const float* __restrict__ k55, const float* __restrict__ b55,
                        const float* __restrict__ kx2, const float* __restrict__ bx2,
                        float* __restrict__ out) {
    __shared__ float sv[4][65];
    int idx = blockIdx.x * 256 + threadIdx.x;     // 648 blocks cover 32*81*64
    int o = idx & 63;
    int plin = idx >> 6;                          // b*81 + p
    int ow = plin % 9;
    int oh = (plin / 9) % 9;
    int b = plin / 81;
    float v = b55[o];
    for (int kh = 0; kh < 5; kh++) {
        int h = 2 * oh - 1 + kh;
        if (h < 0 || h > 17) continue;
        for (int kw = 0; kw < 5; kw++) {
            int w = 2 * ow - 1 + kw;
            if (w < 0 || w > 17) continue;
            const float* src = g_t2 + ((b * 18 + h) * 18 + w) * 32;
            const float* wk = k55 + ((kh * 5 + kw) * 32) * 64 + o;
            #pragma unroll 8
            for (int c = 0; c < 32; c++)
                v += src[c] * wk[c * 64];
        }
    }
    sv[threadIdx.x >> 6][o] = v;
    __syncthreads();
    if (threadIdx.x < 32) {
        int pix = threadIdx.x >> 3, o2 = threadIdx.x & 7;
        int plin2 = blockIdx.x * 4 + pix;
        float v2 = bx2[o2];
        #pragma unroll 8
        for (int c = 0; c < 64; c++)
            v2 += sv[pix][c] * kx2[c * 8 + o2];
        out[plin2 * 41 + 1 + o2] = leakyf(v2);
    }
}

// ---------------------------------------------------------------------------
extern "C" void kernel_launch(void* const* d_in, const int* in_sizes, int n_in,
                              void* d_out, int out_size) {
    const float* inp  = (const float*)d_in[0];
    const float* mat  = (const float*)d_in[1];
    const float* w1_k = (const float*)d_in[2];
    const float* w1_b = (const float*)d_in[3];
    const float* x1_k = (const float*)d_in[4];
    const float* x1_b = (const float*)d_in[5];
    const float* c51_k = (const float*)d_in[6];
    const float* c51_b = (const float*)d_in[7];
    const float* c15_k = (const float*)d_in[8];
    const float* c15_b = (const float*)d_in[9];
    const float* c55_k = (const float*)d_in[10];
    const float* c55_b = (const float*)d_in[11];
    const float* x2_k = (const float*)d_in[12];
    const float* x2_b = (const float*)d_in[13];
    const float* y17_k = (const float*)d_in[14];
    const float* y17_b = (const float*)d_in[15];
    const float* y71_k = (const float*)d_in[16];
    const float* y71_b = (const float*)d_in[17];
    const float* yc_k = (const float*)d_in[18];
    const float* yc_b = (const float*)d_in[19];
    const float* d1_k = (const float*)d_in[20];
    const float* d2_k = (const float*)d_in[21];
    const float* h1_w = (const float*)d_in[22];
    const float* h1_b = (const float*)d_in[23];
    const float* h2_w = (const float*)d_in[24];
    const float* h2_b = (const float*)d_in[25];
    const float* h3_w = (const float*)d_in[26];
    const float* h3_b = (const float*)d_in[27];

    float* out = (float*)d_out;
    const int OUT1 = 32 * 9 * 9 * 41;              // 106272
    const int OUT2 = 32 * 72 * 72 * 3;             // 497664
    float* cs_extra = (out_size >= OUT1 + OUT2) ? (out + OUT1) : nullptr;

    k_main<<<128, 576>>>(inp, mat, w1_k, w1_b, x1_k, x1_b, y17_k, y17_b,
                         y71_k, y71_b, yc_k, yc_b, d1_k, d2_k,
                         h1_w, h1_b, h2_w, h2_b, h3_w, h3_b, out, cs_extra);
    k_c51<<<(32 * 36 * 36 * 16 + 255) / 256, 256>>>(c51_k, c51_b);
    k_c15<<<(32 * 18 * 18 * 32 + 255) / 256, 256>>>(c15_k, c15_b);
    k_c55x2<<<648, 256>>>(c55_k, c55_b, x2_k, x2_b, out);
}